// round 14
// baseline (speedup 1.0000x reference)
#include <cuda_runtime.h>
#include <cuda_fp16.h>
#include <cstdint>

#define BB 2
#define CC 256
#define NHEAD 4
#define HD 64
#define NTOK 4096

// ---------------- device scratch (fp16) ----------------
__device__ __half g_xq[BB*NTOK*CC];         // GN(input)^T  [b][tok][ch]
__device__ __half g_xk[BB*NTOK*CC];         // GN(c)^T      [b][tok][ch]
__device__ __half g_qb[BB*NHEAD*NTOK*HD];   // [bh][tok][d]  (pre-scaled by CEXP)
__device__ __half g_kb[BB*NHEAD*NTOK*HD];   // [bh][tok][d]
__device__ __half g_vb[BB*NHEAD*HD*NTOK];   // [bh][d][tok]
__device__ __half g_ob[BB*NTOK*CC];         // attn out     [b][tok][ch]

// ---------------- helpers ----------------
__device__ __forceinline__ void mma_f32(float* c, uint32_t a0, uint32_t a1, uint32_t a2,
                                        uint32_t a3, uint32_t b0, uint32_t b1) {
    asm volatile(
        "mma.sync.aligned.m16n8k16.row.col.f32.f16.f16.f32 "
        "{%0,%1,%2,%3}, {%4,%5,%6,%7}, {%8,%9}, {%0,%1,%2,%3};"
        : "+f"(c[0]), "+f"(c[1]), "+f"(c[2]), "+f"(c[3])
        : "r"(a0), "r"(a1), "r"(a2), "r"(a3), "r"(b0), "r"(b1));
}
__device__ __forceinline__ void mma_h16(uint32_t* c, uint32_t a0, uint32_t a1, uint32_t a2,
                                        uint32_t a3, uint32_t b0, uint32_t b1) {
    asm volatile(
        "mma.sync.aligned.m16n8k16.row.col.f16.f16.f16.f16 "
        "{%0,%1}, {%2,%3,%4,%5}, {%6,%7}, {%0,%1};"
        : "+r"(c[0]), "+r"(c[1])
        : "r"(a0), "r"(a1), "r"(a2), "r"(a3), "r"(b0), "r"(b1));
}
__device__ __forceinline__ uint32_t ex2h2(uint32_t x) {
    uint32_t r;
    asm("ex2.approx.f16x2 %0, %1;" : "=r"(r) : "r"(x));
    return r;
}
__device__ __forceinline__ uint32_t hadd2u(uint32_t a, uint32_t b) {
    uint32_t r;
    asm("add.f16x2 %0, %1, %2;" : "=r"(r) : "r"(a), "r"(b));
    return r;
}
__device__ __forceinline__ float2 h22f2(uint32_t u) {
    __half2 h = *reinterpret_cast<__half2*>(&u);
    return __half22float2(h);
}
__device__ __forceinline__ uint32_t packh2(float lo, float hi) {
    __half2 h = __floats2half2_rn(lo, hi);
    return *reinterpret_cast<uint32_t*>(&h);
}
__device__ __forceinline__ uint32_t smem_u32(const void* p) {
    uint32_t a;
    asm("{ .reg .u64 t; cvta.to.shared.u64 t, %1; cvt.u32.u64 %0, t; }" : "=r"(a) : "l"(p));
    return a;
}
__device__ __forceinline__ void ldsm_x4(uint32_t& r0, uint32_t& r1, uint32_t& r2, uint32_t& r3,
                                        uint32_t addr) {
    asm volatile("ldmatrix.sync.aligned.m8n8.x4.shared.b16 {%0,%1,%2,%3}, [%4];"
                 : "=r"(r0), "=r"(r1), "=r"(r2), "=r"(r3) : "r"(addr));
}
__device__ __forceinline__ void cp16(uint32_t saddr, const void* g) {
    asm volatile("cp.async.cg.shared.global [%0], [%1], 16;" :: "r"(saddr), "l"(g));
}
#define CP_COMMIT() asm volatile("cp.async.commit_group;" ::: "memory")
#define CP_WAIT(n)  asm volatile("cp.async.wait_group %0;" :: "n"(n) : "memory")

// ---------------- GroupNorm -> fp16 X^T [b][tok][256] (fused both sources) ----------------
__global__ __launch_bounds__(256) void gn_xt_kernel(const float* __restrict__ src0,
                                                    const float* __restrict__ src1,
                                                    const float* __restrict__ gw,
                                                    const float* __restrict__ gb) {
    int which = blockIdx.y;
    const float* src = which ? src1 : src0;
    int b = blockIdx.x >> 5, g = blockIdx.x & 31;
    size_t base = ((size_t)b * CC + g * 8) * NTOK;
    const float4* s4 = reinterpret_cast<const float4*>(src + base);
    int tid = threadIdx.x;

    float sum = 0.f, ssq = 0.f;
#pragma unroll
    for (int i = 0; i < 32; i++) {
        float4 v = s4[tid + i * 256];
        sum += v.x + v.y + v.z + v.w;
        ssq += v.x * v.x + v.y * v.y + v.z * v.z + v.w * v.w;
    }
#pragma unroll
    for (int off = 16; off; off >>= 1) {
        sum += __shfl_xor_sync(0xffffffffu, sum, off);
        ssq += __shfl_xor_sync(0xffffffffu, ssq, off);
    }
    __shared__ float r1[8], r2[8];
    if ((tid & 31) == 0) { r1[tid >> 5] = sum; r2[tid >> 5] = ssq; }
    __syncthreads();
    sum = 0.f; ssq = 0.f;
#pragma unroll
    for (int i = 0; i < 8; i++) { sum += r1[i]; ssq += r2[i]; }
    float mean = sum * (1.f / 32768.f);
    float var  = ssq * (1.f / 32768.f) - mean * mean;
    float rstd = rsqrtf(var + 1e-5f);

    float a[8], c0[8];
#pragma unroll
    for (int ch = 0; ch < 8; ch++) {
        a[ch]  = gw[g * 8 + ch] * rstd;
        c0[ch] = gb[g * 8 + ch] - mean * a[ch];
    }
    __half* xt = (which ? g_xk : g_xq) + (size_t)b * NTOK * CC + g * 8;
#pragma unroll
    for (int i = 0; i < 16; i++) {
        int tok = tid + i * 256;
        float v[8];
#pragma unroll
        for (int ch = 0; ch < 8; ch++)
            v[ch] = src[base + (size_t)ch * NTOK + tok] * a[ch] + c0[ch];
        uint4 u = {packh2(v[0], v[1]), packh2(v[2], v[3]),
                   packh2(v[4], v[5]), packh2(v[6], v[7])};
        *reinterpret_cast<uint4*>(xt + (size_t)tok * CC) = u;
    }
}

// ---------------- QKV projection: roles 0-3 = q head, 4-7 = fused k+v head ----------------
// dynamic smem: XTs[2][128*72] + Ws[128*72]  (55296 B)
#define QKV_SMEM ((2 * 128 * 72 + 128 * 72) * 2)

__global__ __launch_bounds__(256) void qkv_kernel(const float* __restrict__ wq,
                                                  const float* __restrict__ wkv) {
    extern __shared__ __half qsm[];
    __half* XT0 = qsm;
    __half* XT1 = qsm + 128 * 72;
    __half* Ws  = qsm + 2 * 128 * 72;

    int tid = threadIdx.x, wid = tid >> 5, lane = tid & 31;
    int r0 = lane >> 2, cp = (lane & 3) << 1;
    int nx = blockIdx.x, role = blockIdx.y, b = blockIdx.z;

    bool is_q = (role < 4);
    int h = is_q ? role : role - 4;
    const float* W = is_q ? wq + (size_t)h * 64 * CC : wkv + (size_t)h * 128 * CC;
    const __half* X = (is_q ? g_xq : g_xk) + (size_t)b * NTOK * CC;
    int wrows = is_q ? 64 : 128;
    int bh = b * NHEAD + h;

    uint32_t xbase[2] = {smem_u32(XT0), smem_u32(XT1)};
    __half* XTp[2] = {XT0, XT1};

    auto load_x = [&](int k0, int st) {
#pragma unroll
        for (int i = 0; i < 4; i++) {
            int idx = tid + i * 256;
            int r = idx >> 3, c8 = idx & 7;
            cp16(xbase[st] + (r * 72 + c8 * 8) * 2,
                 X + ((size_t)(nx * 128 + r)) * CC + k0 + c8 * 8);
        }
    };

    load_x(0, 0);
    CP_COMMIT();

    float acc[8][4] = {};      // q or k accumulators
    float accv[8][4] = {};     // v accumulators (kv role only)

    for (int kc = 0; kc < 4; kc++) {
        int k0 = kc * 64, st = kc & 1;
        // W chunk (synchronous; L2-resident across nx-CTAs)
        for (int i = 0; i < 8; i++) {
            int idx = tid + i * 256;
            if (idx >= wrows * 16) break;
            int r = idx >> 4, c4 = (idx & 15) << 2;
            float4 w4 = *reinterpret_cast<const float4*>(W + (size_t)r * CC + k0 + c4);
            *reinterpret_cast<uint32_t*>(&Ws[r * 72 + c4])     = packh2(w4.x, w4.y);
            *reinterpret_cast<uint32_t*>(&Ws[r * 72 + c4 + 2]) = packh2(w4.z, w4.w);
        }
        CP_WAIT(0);
        __syncthreads();
        if (kc + 1 < 4) { load_x(k0 + 64, st ^ 1); CP_COMMIT(); }

        const __half* Xc = XTp[st];
        // q / k part: C[tok][outch], A = X rows, B = Ws rows 0..63
#pragma unroll
        for (int ks = 0; ks < 4; ks++) {
            const __half* Ar = Xc + (wid * 16 + r0) * 72 + ks * 16 + cp;
            uint32_t a0 = *reinterpret_cast<const uint32_t*>(Ar);
            uint32_t a1 = *reinterpret_cast<const uint32_t*>(Ar + 8 * 72);
            uint32_t a2 = *reinterpret_cast<const uint32_t*>(Ar + 8);
            uint32_t a3 = *reinterpret_cast<const uint32_t*>(Ar + 8 * 72 + 8);
#pragma unroll
            for (int nt = 0; nt < 8; nt++) {
                const __half* Br = Ws + (nt * 8 + r0) * 72 + ks * 16 + cp;
                uint32_t b0 = *reinterpret_cast<const uint32_t*>(Br);
                uint32_t b1 = *reinterpret_cast<const uint32_t*>(Br + 8);
                mma_f32(acc[nt], a0, a1, a2, a3, b0, b1);
            }
        }
        // v part (kv role): C[outch][tok], A = Ws rows 64..127, B = X rows
        if (!is_q) {
#pragma unroll
            for (int ks = 0; ks < 4; ks++) {
                const __half* Ar = Ws + (64 + (wid & 3) * 16 + r0) * 72 + ks * 16 + cp;
                uint32_t a0 = *reinterpret_cast<const uint32_t*>(Ar);
                uint32_t a1 = *reinterpret_cast<const uint32_t*>(Ar + 8 * 72);
                uint32_t a2 = *reinterpret_cast<const uint32_t*>(Ar + 8);
                uint32_t a3 = *reinterpret_cast<const uint32_t*>(Ar + 8 * 72 + 8);
#pragma unroll
                for (int nt = 0; nt < 8; nt++) {
                    const __half* Br = Xc + ((wid >> 2) * 64 + nt * 8 + r0) * 72 + ks * 16 + cp;
                    uint32_t b0 = *reinterpret_cast<const uint32_t*>(Br);
                    uint32_t b1 = *reinterpret_cast<const uint32_t*>(Br + 8);
                    mma_f32(accv[nt], a0, a1, a2, a3, b0, b1);
                }
            }
        }
        __syncthreads();   // Ws + XT reused next iter
    }

    // epilogue: q or k (C[tok][64] -> [bh][tok][64])
    {
        float qs = is_q ? 0.09016844f : 1.0f;   // (1/16)*log2(e) folded into q
        __half* stage = XT0;
        int row = wid * 16 + r0;
#pragma unroll
        for (int nt = 0; nt < 8; nt++) {
            int col = nt * 8 + cp;
            *reinterpret_cast<uint32_t*>(&stage[row * 72 + col])       = packh2(acc[nt][0] * qs, acc[nt][1] * qs);
            *reinterpret_cast<uint32_t*>(&stage[(row + 8) * 72 + col]) = packh2(acc[nt][2] * qs, acc[nt][3] * qs);
        }
        __syncthreads();
        __half* dst = (is_q ? g_qb : g_kb) + ((size_t)bh * NTOK + nx * 128) * 64;
#pragma unroll
        for (int i = 0; i < 4; i++) {
            int idx = tid + i * 256;
            int r = idx >> 3, c8 = idx & 7;
            *reinterpret_cast<uint4*>(dst + (size_t)r * 64 + c8 * 8) =
                *reinterpret_cast<uint4*>(&stage[r * 72 + c8 * 8]);
        }
    }
    // epilogue: v (C[64][128] -> [bh][d][tok])
    if (!is_q) {
        __syncthreads();
        __half* stage = XT0;   // reused as [64][136]
        int chrow = (wid & 3) * 16 + r0;
#pragma unroll
        for (int nt = 0; nt < 8; nt++) {
            int col = (wid >> 2) * 64 + nt * 8 + cp;
            *reinterpret_cast<uint32_t*>(&stage[chrow * 136 + col])       = packh2(accv[nt][0], accv[nt][1]);
            *reinterpret_cast<uint32_t*>(&stage[(chrow + 8) * 136 + col]) = packh2(accv[nt][2], accv[nt][3]);
        }
        __syncthreads();
        __half* dst = g_vb + (size_t)bh * HD * NTOK + nx * 128;
#pragma unroll
        for (int i = 0; i < 4; i++) {
            int idx = tid + i * 256;
            int r = idx >> 4, c16 = idx & 15;
            *reinterpret_cast<uint4*>(dst + (size_t)r * NTOK + c16 * 8) =
                *reinterpret_cast<uint4*>(&stage[r * 136 + c16 * 8]);
        }
    }
}

// ---------------- HMMA flash attention (unchanged) ----------------
#define AQ_SZ   (128 * 72)
#define AK_SZ   (128 * 72)
#define AV_SZ   (64 * 136)
#define STG_SZ  (AK_SZ + AV_SZ)
#define ATTN_SMEM ((AQ_SZ + 2 * STG_SZ) * 2)

__global__ __launch_bounds__(128, 2) void attn_mma_kernel() {
    extern __shared__ __half sm[];
    __half* Qsm = sm;

    int tid = threadIdx.x, wid = tid >> 5, lane = tid & 31;
    int qb = blockIdx.x, bh = blockIdx.y;

    uint32_t sbase = smem_u32(sm);
    uint32_t Qb = sbase;
    uint32_t Kb[2] = {sbase + AQ_SZ * 2, sbase + (AQ_SZ + STG_SZ) * 2};
    uint32_t Vb[2] = {Kb[0] + AK_SZ * 2, Kb[1] + AK_SZ * 2};

    const __half* Kg_base = g_kb + (size_t)bh * NTOK * 64;
    const __half* Vg_base = g_vb + (size_t)bh * 64 * NTOK;

    auto load_kv = [&](int kb, int st) {
#pragma unroll
        for (int i = 0; i < 8; i++) {
            int idx = tid + i * 128;
            int r = idx >> 3, c8 = idx & 7;
            cp16(Kb[st] + (r * 72 + c8 * 8) * 2,
                 Kg_base + ((size_t)(kb * 128 + r)) * 64 + c8 * 8);
        }
#pragma unroll
        for (int i = 0; i < 8; i++) {
            int idx = tid + i * 128;
            int r = idx >> 4, c16 = idx & 15;
            cp16(Vb[st] + (r * 136 + c16 * 8) * 2,
                 Vg_base + (size_t)r * NTOK + kb * 128 + c16 * 8);
        }
    };

    {
        const uint4* Qg = reinterpret_cast<const uint4*>(g_qb + ((size_t)bh * NTOK + qb * 128) * 64);
#pragma unroll
        for (int i = 0; i < 8; i++) {
            int idx = tid + i * 128;
            int r = idx >> 3, c8 = idx & 7;
            *reinterpret_cast<uint4*>(Qsm + r * 72 + c8 * 8) = Qg[idx];
        }
    }
    load_kv(0, 0);
    CP_COMMIT();
    __syncthreads();

    uint32_t qf[2][4][4];
#pragma unroll
    for (int t = 0; t < 2; t++)
#pragma unroll
        for (int ks = 0; ks < 4; ks++) {
            uint32_t addr = Qb + ((wid * 32 + t * 16 + (lane & 15)) * 72 + ks * 16 + (lane >> 4) * 8) * 2;
            ldsm_x4(qf[t][ks][0], qf[t][ks][1], qf[t][ks][2], qf[t][ks][3], addr);
        }

    float oacc[2][8][4] = {};
    float l0[2] = {0.f, 0.f}, l1[2] = {0.f, 0.f};

    int btok = ((lane >> 4) << 3) + (lane & 7);
    int bk8  = lane & 8;

    for (int kb = 0; kb < 32; kb++) {
        int st = kb & 1;
        CP_WAIT(0);
        __syncthreads();
        if (kb + 1 < 32) { load_kv(kb + 1, st ^ 1); CP_COMMIT(); }

        uint32_t op[2][8][2] = {};

#pragma unroll
        for (int kt = 0; kt < 8; kt++) {
            uint32_t kf[4][4];
            {
                uint32_t ka = Kb[st] + ((kt * 16 + btok) * 72 + bk8) * 2;
#pragma unroll
                for (int ks = 0; ks < 4; ks++)
                    ldsm_x4(kf[ks][0], kf[ks][1], kf[ks][2], kf[ks][3], ka + ks * 32);
            }
            uint32_t vf[4][4];
            {
                uint32_t va = Vb[st] + (btok * 136 + kt * 16 + bk8) * 2;
#pragma unroll
                for (int j = 0; j < 4; j++)
                    ldsm_x4(vf[j][0], vf[j][1], vf[j][2], vf[j][3], va + j * 16 * 136 * 2);
            }

            uint32_t s[2][2][2] = {};
#pragma unroll
            for (int ks = 0; ks < 4; ks++) {
#pragma unroll
                for (int t = 0; t < 2; t++) {
                    mma_h16(s[t][0], qf[t][ks][0], qf[t][ks][1], qf[t][ks][2], qf[t][ks][3], kf[ks][0], kf[ks][1]);
                    mma_h16(s[t][1], qf[t][ks][0], qf[t][ks][1], qf[t][ks][2], qf[t][ks][3], kf[ks][2], kf[ks][3]);
                }
            }

#pragma unroll
            for (int t = 0; t < 2; t++) {
                uint32_t a0 = ex2h2(s[t][0][0]);
                uint32_t a1 = ex2h2(s[t][0][1]);
                uint32_t a2 = ex2h2(s[t][1][0]);
                uint32_t a3 = ex2h2(s[t][1][1]);
                float2 f0 = h22f2(hadd2u(a0, a2));
                float2 f1 = h22f2(hadd2u(a1, a3));
                l0[t] += f0.x + f0.y;
                l1[t] += f1.x + f1.y;
#pragma unroll
                for (int j = 0; j < 4; j++) {
                    mma_h16(op[t][2 * j],     a0, a1, a2, a3, vf[j][0], vf[j][1]);
                    mma_h16(op[t][2 * j + 1], a0, a1, a2, a3, vf[j][2], vf[j][3]);
                }
            }
        }

#pragma unroll
        for (int t = 0; t < 2; t++)
#pragma unroll
            for (int nt = 0; nt < 8; nt++) {
                float2 f0 = h22f2(op[t][nt][0]);
                float2 f1 = h22f2(op[t][nt][1]);
                oacc[t][nt][0] += f0.x; oacc[t][nt][1] += f0.y;
                oacc[t][nt][2] += f1.x; oacc[t][nt][3] += f1.y;
            }
    }

#pragma unroll
    for (int t = 0; t < 2; t++) {
        l0[t] += __shfl_xor_sync(0xffffffffu, l0[t], 1);
        l0[t] += __shfl_xor_sync(0xffffffffu, l0[t], 2);
        l1[t] += __shfl_xor_sync(0xffffffffu, l1[t], 1);
        l1[t] += __shfl_xor_sync(0xffffffffu, l1[t], 2);
    }

    __syncthreads();
    int r0 = lane >> 2, cpair = (lane & 3) << 1;
#pragma unroll
    for (int t = 0; t < 2; t++) {
        float inv0 = 1.f / l0[t], inv1 = 1.f / l1[t];
        int row = wid * 32 + t * 16 + r0;
#pragma unroll
        for (int nt = 0; nt < 8; nt++) {
            int col = nt * 8 + cpair;
            *reinterpret_cast<uint32_t*>(&Qsm[row * 72 + col])       = packh2(oacc[t][nt][0] * inv0, oacc[t][nt][1] * inv0);
            *reinterpret_cast<uint32_t*>(&Qsm[(row + 8) * 72 + col]) = packh2(oacc[t][nt][2] * inv1, oacc[t][nt][3] * inv1);
        }
    }
    __syncthreads();
    {
        int b = bh >> 2, h = bh & 3;
        __half* dst = g_ob + ((size_t)b * NTOK + qb * 128) * CC + h * 64;
#pragma unroll
        for (int i = 0; i < 8; i++) {
            int idx = tid + i * 128;
            int r = idx >> 3, c8 = idx & 7;
            *reinterpret_cast<uint4*>(dst + (size_t)r * CC + c8 * 8) =
                *reinterpret_cast<uint4*>(&Qsm[r * 72 + c8 * 8]);
        }
    }
}

// ---------------- output projection: 64-token tiles, grid (64,4,2) ----------------
__global__ __launch_bounds__(256) void out_kernel(const float* __restrict__ wout,
                                                  const float* __restrict__ wout_b,
                                                  const float* __restrict__ inp,
                                                  float* __restrict__ out) {
    __shared__ __half XTs[2][64 * 72];
    __shared__ __half Ws[64 * 72];

    int tid = threadIdx.x, wid = tid >> 5, lane = tid & 31;
    int r0 = lane >> 2, cp = (lane & 3) << 1;
    int nx = blockIdx.x, my = blockIdx.y, b = blockIdx.z;

    const float* W = wout + (size_t)my * 64 * CC;
    const __half* X = g_ob + (size_t)b * NTOK * CC;

    uint32_t xbase[2] = {smem_u32(&XTs[0][0]), smem_u32(&XTs[1][0])};

    auto load_x = [&](int k0, int st) {
#pragma unroll
        for (int i = 0; i < 2; i++) {
            int idx = tid + i * 256;
            int r = idx >> 3, c8 = idx & 7;
            cp16(xbase[st] + (r * 72 + c8 * 8) * 2,
                 X + ((size_t)(nx * 64 + r)) * CC + k0 + c8 * 8);
        }
    };

    load_x(0, 0);
    CP_COMMIT();

    float acc[4][4] = {};

    for (int kc = 0; kc < 4; kc++) {
        int k0 = kc * 64, st = kc & 1;
#pragma unroll
        for (int i = 0; i < 4; i++) {
            int idx = tid + i * 256;
            int r = idx >> 4, c4 = (idx & 15) << 2;
            float4 w4 = *reinterpret_cast<const float4*>(W + (size_t)r * CC + k0 + c4);
            *reinterpret_cast<uint32_t*>(&Ws[r * 72 + c4])     = packh2(w4.x, w4.y);
            *reinterpret_cast<uint32_t*>(&Ws[r * 72 + c4 + 2]) = packh2(w4.z, w4.w);
        }
        CP_WAIT(0);
        __syncthreads();
        if (kc + 1 < 4) { load_x(k0 + 64, st ^ 1); CP_COMMIT(); }

        const __half* Xc = &XTs[st][0];
#pragma unroll
        for (int ks = 0; ks < 4; ks++) {
            const __half* Ar = Ws + ((wid & 3) * 16 + r0) * 72 + ks * 16 + cp;
            uint32_t a0 = *reinterpret_cast<const uint32_t*>(Ar);
            uint32_t a1 = *reinterpret_cast<const uint32_t*>(Ar + 8 * 72);
            uint32_t a2 = *reinterpret_cast<const uint32_t*>(Ar + 8);
            uint32_t a3 = *reinterpret_cast<const uint32_t*>(Ar + 8 * 72 + 8);
#pragma unroll
            for (int nt = 0; nt < 4; nt++) {
                const __half* Br = Xc + ((wid >> 2) * 32 + nt * 8 + r0) * 72 + ks * 16 + cp;
                uint32_t b0 = *reinterpret_cast<const uint32_t*>(Br);
                uint32_t b1 = *reinterpret_cast<const uint32_t*>(Br + 8);
                mma_f32(acc[nt], a0, a1, a2, a3, b0, b1);
            }
        }
        __syncthreads();
    }

    {
        int ch0 = my * 64 + (wid & 3) * 16 + r0;
        float bias0 = wout_b[ch0], bias1 = wout_b[ch0 + 8];
#pragma unroll
        for (int nt = 0; nt < 4; nt++) {
            int col = nx * 64 + (wid >> 2) * 32 + nt * 8 + cp;
            size_t off0 = ((size_t)b * CC + ch0) * NTOK + col;
            size_t off1 = off0 + (size_t)8 * NTOK;
            float2 rin0 = *reinterpret_cast<const float2*>(inp + off0);
            float2 rin1 = *reinterpret_cast<const float2*>(inp + off1);
            float2 v0 = {acc[nt][0] + bias0 + rin0.x, acc[nt][1] + bias0 + rin0.y};
            float2 v1 = {acc[nt][2] + bias1 + rin1.x, acc[nt][3] + bias1 + rin1.y};
            *reinterpret_cast<float2*>(out + off0) = v0;
            *reinterpret_cast<float2*>(out + off1) = v1;
        }
    }
}

// ---------------- launch ----------------
extern "C" void kernel_launch(void* const* d_in, const int* in_sizes, int n_in,
                              void* d_out, int out_size) {
    const float* input  = (const float*)d_in[0];
    const float* cctx   = (const float*)d_in[1];
    const float* gn_w   = (const float*)d_in[2];
    const float* gn_b   = (const float*)d_in[3];
    const float* wq     = (const float*)d_in[4];
    const float* wkv    = (const float*)d_in[5];
    const float* wout_w = (const float*)d_in[6];
    const float* wout_b = (const float*)d_in[7];
    float* out = (float*)d_out;

    static int smem_set = 0;
    if (!smem_set) {
        cudaFuncSetAttribute(attn_mma_kernel, cudaFuncAttributeMaxDynamicSharedMemorySize, ATTN_SMEM);
        cudaFuncSetAttribute(qkv_kernel, cudaFuncAttributeMaxDynamicSharedMemorySize, QKV_SMEM);
        smem_set = 1;
    }

    gn_xt_kernel<<<dim3(64, 2), 256>>>(input, cctx, gn_w, gn_b);
    qkv_kernel<<<dim3(32, 8, BB), 256, QKV_SMEM>>>(wq, wkv);
    attn_mma_kernel<<<dim3(32, BB * NHEAD), 128, ATTN_SMEM>>>();
    out_kernel<<<dim3(64, 4, BB), 256>>>(wout_w, wout_b, input, out);
}

// round 15
// speedup vs baseline: 1.0197x; 1.0197x over previous
#include <cuda_runtime.h>
#include <cuda_fp16.h>
#include <cstdint>

#define BB 2
#define CC 256
#define NHEAD 4
#define HD 64
#define NTOK 4096

// ---------------- device scratch (fp16) ----------------
__device__ __half g_xq[BB*NTOK*CC];         // GN(input)^T  [b][tok][ch]
__device__ __half g_xk[BB*NTOK*CC];         // GN(c)^T      [b][tok][ch]
__device__ __half g_qb[BB*NHEAD*NTOK*HD];   // [bh][tok][d]  (pre-scaled by CEXP)
__device__ __half g_kb[BB*NHEAD*NTOK*HD];   // [bh][tok][d]
__device__ __half g_vb[BB*NHEAD*HD*NTOK];   // [bh][d][tok]
__device__ __half g_ob[BB*NTOK*CC];         // attn out     [b][tok][ch]

// ---------------- helpers ----------------
__device__ __forceinline__ void mma_f32(float* c, uint32_t a0, uint32_t a1, uint32_t a2,
                                        uint32_t a3, uint32_t b0, uint32_t b1) {
    asm volatile(
        "mma.sync.aligned.m16n8k16.row.col.f32.f16.f16.f32 "
        "{%0,%1,%2,%3}, {%4,%5,%6,%7}, {%8,%9}, {%0,%1,%2,%3};"
        : "+f"(c[0]), "+f"(c[1]), "+f"(c[2]), "+f"(c[3])
        : "r"(a0), "r"(a1), "r"(a2), "r"(a3), "r"(b0), "r"(b1));
}
__device__ __forceinline__ void mma_h16(uint32_t* c, uint32_t a0, uint32_t a1, uint32_t a2,
                                        uint32_t a3, uint32_t b0, uint32_t b1) {
    asm volatile(
        "mma.sync.aligned.m16n8k16.row.col.f16.f16.f16.f16 "
        "{%0,%1}, {%2,%3,%4,%5}, {%6,%7}, {%0,%1};"
        : "+r"(c[0]), "+r"(c[1])
        : "r"(a0), "r"(a1), "r"(a2), "r"(a3), "r"(b0), "r"(b1));
}
__device__ __forceinline__ uint32_t ex2h2(uint32_t x) {
    uint32_t r;
    asm("ex2.approx.f16x2 %0, %1;" : "=r"(r) : "r"(x));
    return r;
}
__device__ __forceinline__ uint32_t hadd2u(uint32_t a, uint32_t b) {
    uint32_t r;
    asm("add.f16x2 %0, %1, %2;" : "=r"(r) : "r"(a), "r"(b));
    return r;
}
__device__ __forceinline__ float2 h22f2(uint32_t u) {
    __half2 h = *reinterpret_cast<__half2*>(&u);
    return __half22float2(h);
}
__device__ __forceinline__ uint32_t packh2(float lo, float hi) {
    __half2 h = __floats2half2_rn(lo, hi);
    return *reinterpret_cast<uint32_t*>(&h);
}
__device__ __forceinline__ uint32_t smem_u32(const void* p) {
    uint32_t a;
    asm("{ .reg .u64 t; cvta.to.shared.u64 t, %1; cvt.u32.u64 %0, t; }" : "=r"(a) : "l"(p));
    return a;
}
__device__ __forceinline__ void ldsm_x4(uint32_t& r0, uint32_t& r1, uint32_t& r2, uint32_t& r3,
                                        uint32_t addr) {
    asm volatile("ldmatrix.sync.aligned.m8n8.x4.shared.b16 {%0,%1,%2,%3}, [%4];"
                 : "=r"(r0), "=r"(r1), "=r"(r2), "=r"(r3) : "r"(addr));
}
__device__ __forceinline__ void cp16(uint32_t saddr, const void* g) {
    asm volatile("cp.async.cg.shared.global [%0], [%1], 16;" :: "r"(saddr), "l"(g));
}
#define CP_COMMIT() asm volatile("cp.async.commit_group;" ::: "memory")
#define CP_WAIT(n)  asm volatile("cp.async.wait_group %0;" :: "n"(n) : "memory")

// ---------------- GroupNorm -> fp16 X^T [b][tok][256], vectorized 2nd pass ----------------
__global__ __launch_bounds__(256) void gn_xt_kernel(const float* __restrict__ src0,
                                                    const float* __restrict__ src1,
                                                    const float* __restrict__ gw,
                                                    const float* __restrict__ gb) {
    int which = blockIdx.y;
    const float* src = which ? src1 : src0;
    int b = blockIdx.x >> 5, g = blockIdx.x & 31;
    size_t base = ((size_t)b * CC + g * 8) * NTOK;
    const float4* s4 = reinterpret_cast<const float4*>(src + base);
    int tid = threadIdx.x;

    float sum = 0.f, ssq = 0.f;
#pragma unroll
    for (int i = 0; i < 32; i++) {
        float4 v = s4[tid + i * 256];
        sum += v.x + v.y + v.z + v.w;
        ssq += v.x * v.x + v.y * v.y + v.z * v.z + v.w * v.w;
    }
#pragma unroll
    for (int off = 16; off; off >>= 1) {
        sum += __shfl_xor_sync(0xffffffffu, sum, off);
        ssq += __shfl_xor_sync(0xffffffffu, ssq, off);
    }
    __shared__ float r1[8], r2[8];
    if ((tid & 31) == 0) { r1[tid >> 5] = sum; r2[tid >> 5] = ssq; }
    __syncthreads();
    sum = 0.f; ssq = 0.f;
#pragma unroll
    for (int i = 0; i < 8; i++) { sum += r1[i]; ssq += r2[i]; }
    float mean = sum * (1.f / 32768.f);
    float var  = ssq * (1.f / 32768.f) - mean * mean;
    float rstd = rsqrtf(var + 1e-5f);

    float a[8], c0[8];
#pragma unroll
    for (int ch = 0; ch < 8; ch++) {
        a[ch]  = gw[g * 8 + ch] * rstd;
        c0[ch] = gb[g * 8 + ch] - mean * a[ch];
    }
    __half* xt = (which ? g_xk : g_xq) + (size_t)b * NTOK * CC + g * 8;
    // pass 2: 4 tokens per thread per iteration, float4 loads per channel
#pragma unroll
    for (int i = 0; i < 4; i++) {
        int tok0 = (tid + i * 256) * 4;
        float4 vv[8];
#pragma unroll
        for (int ch = 0; ch < 8; ch++) {
            float4 v = *reinterpret_cast<const float4*>(src + base + (size_t)ch * NTOK + tok0);
            vv[ch].x = v.x * a[ch] + c0[ch];
            vv[ch].y = v.y * a[ch] + c0[ch];
            vv[ch].z = v.z * a[ch] + c0[ch];
            vv[ch].w = v.w * a[ch] + c0[ch];
        }
        {
            uint4 u = {packh2(vv[0].x, vv[1].x), packh2(vv[2].x, vv[3].x),
                       packh2(vv[4].x, vv[5].x), packh2(vv[6].x, vv[7].x)};
            *reinterpret_cast<uint4*>(xt + (size_t)(tok0 + 0) * CC) = u;
        }
        {
            uint4 u = {packh2(vv[0].y, vv[1].y), packh2(vv[2].y, vv[3].y),
                       packh2(vv[4].y, vv[5].y), packh2(vv[6].y, vv[7].y)};
            *reinterpret_cast<uint4*>(xt + (size_t)(tok0 + 1) * CC) = u;
        }
        {
            uint4 u = {packh2(vv[0].z, vv[1].z), packh2(vv[2].z, vv[3].z),
                       packh2(vv[4].z, vv[5].z), packh2(vv[6].z, vv[7].z)};
            *reinterpret_cast<uint4*>(xt + (size_t)(tok0 + 2) * CC) = u;
        }
        {
            uint4 u = {packh2(vv[0].w, vv[1].w), packh2(vv[2].w, vv[3].w),
                       packh2(vv[4].w, vv[5].w), packh2(vv[6].w, vv[7].w)};
            *reinterpret_cast<uint4*>(xt + (size_t)(tok0 + 3) * CC) = u;
        }
    }
}

// ---------------- QKV projection via HMMA (X tiles double-buffered via cp.async) ----------------
__global__ __launch_bounds__(256) void qkv_kernel(const float* __restrict__ wq,
                                                  const float* __restrict__ wkv) {
    __shared__ __half XTs[2][128 * 72];
    __shared__ __half Ws[64 * 72];

    int tid = threadIdx.x, wid = tid >> 5, lane = tid & 31;
    int r0 = lane >> 2, cp = (lane & 3) << 1;
    int nx = blockIdx.x, role = blockIdx.y, b = blockIdx.z;

    const float* W;
    const __half* X;
    int h;
    bool is_v = (role >= 8);
    if (role < 4)      { h = role;     W = wq  + (size_t)h * 64 * CC;          X = g_xq + (size_t)b * NTOK * CC; }
    else if (role < 8) { h = role - 4; W = wkv + (size_t)(h * 128) * CC;       X = g_xk + (size_t)b * NTOK * CC; }
    else               { h = role - 8; W = wkv + (size_t)(h * 128 + 64) * CC;  X = g_xk + (size_t)b * NTOK * CC; }
    int bh = b * NHEAD + h;

    uint32_t xbase[2] = {smem_u32(&XTs[0][0]), smem_u32(&XTs[1][0])};

    auto load_x = [&](int k0, int st) {
#pragma unroll
        for (int i = 0; i < 4; i++) {
            int idx = tid + i * 256;
            int r = idx >> 3, c8 = idx & 7;
            cp16(xbase[st] + (r * 72 + c8 * 8) * 2,
                 X + ((size_t)(nx * 128 + r)) * CC + k0 + c8 * 8);
        }
    };

    load_x(0, 0);
    CP_COMMIT();

    float acc[8][4] = {};

    for (int kc = 0; kc < 4; kc++) {
        int k0 = kc * 64, st = kc & 1;
#pragma unroll
        for (int i = 0; i < 4; i++) {
            int idx = tid + i * 256;
            int r = idx >> 4, c4 = (idx & 15) << 2;
            float4 w4 = *reinterpret_cast<const float4*>(W + (size_t)r * CC + k0 + c4);
            *reinterpret_cast<uint32_t*>(&Ws[r * 72 + c4])     = packh2(w4.x, w4.y);
            *reinterpret_cast<uint32_t*>(&Ws[r * 72 + c4 + 2]) = packh2(w4.z, w4.w);
        }
        CP_WAIT(0);
        __syncthreads();
        if (kc + 1 < 4) { load_x(k0 + 64, st ^ 1); CP_COMMIT(); }

        const __half* Xc = &XTs[st][0];
        if (!is_v) {
#pragma unroll
            for (int ks = 0; ks < 4; ks++) {
                const __half* Ar = Xc + (wid * 16 + r0) * 72 + ks * 16 + cp;
                uint32_t a0 = *reinterpret_cast<const uint32_t*>(Ar);
                uint32_t a1 = *reinterpret_cast<const uint32_t*>(Ar + 8 * 72);
                uint32_t a2 = *reinterpret_cast<const uint32_t*>(Ar + 8);
                uint32_t a3 = *reinterpret_cast<const uint32_t*>(Ar + 8 * 72 + 8);
#pragma unroll
                for (int nt = 0; nt < 8; nt++) {
                    const __half* Br = Ws + (nt * 8 + r0) * 72 + ks * 16 + cp;
                    uint32_t b0 = *reinterpret_cast<const uint32_t*>(Br);
                    uint32_t b1 = *reinterpret_cast<const uint32_t*>(Br + 8);
                    mma_f32(acc[nt], a0, a1, a2, a3, b0, b1);
                }
            }
        } else {
#pragma unroll
            for (int ks = 0; ks < 4; ks++) {
                const __half* Ar = Ws + ((wid & 3) * 16 + r0) * 72 + ks * 16 + cp;
                uint32_t a0 = *reinterpret_cast<const uint32_t*>(Ar);
                uint32_t a1 = *reinterpret_cast<const uint32_t*>(Ar + 8 * 72);
                uint32_t a2 = *reinterpret_cast<const uint32_t*>(Ar + 8);
                uint32_t a3 = *reinterpret_cast<const uint32_t*>(Ar + 8 * 72 + 8);
#pragma unroll
                for (int nt = 0; nt < 8; nt++) {
                    const __half* Br = Xc + ((wid >> 2) * 64 + nt * 8 + r0) * 72 + ks * 16 + cp;
                    uint32_t b0 = *reinterpret_cast<const uint32_t*>(Br);
                    uint32_t b1 = *reinterpret_cast<const uint32_t*>(Br + 8);
                    mma_f32(acc[nt], a0, a1, a2, a3, b0, b1);
                }
            }
        }
        __syncthreads();
    }

    if (!is_v) {
        float qs = (role < 4) ? 0.09016844f : 1.0f;   // (1/16)*log2(e) folded into q
        __half* stage = &XTs[0][0];
        int row = wid * 16 + r0;
#pragma unroll
        for (int nt = 0; nt < 8; nt++) {
            int col = nt * 8 + cp;
            *reinterpret_cast<uint32_t*>(&stage[row * 72 + col])       = packh2(acc[nt][0] * qs, acc[nt][1] * qs);
            *reinterpret_cast<uint32_t*>(&stage[(row + 8) * 72 + col]) = packh2(acc[nt][2] * qs, acc[nt][3] * qs);
        }
        __syncthreads();
        __half* dst = (role < 4 ? g_qb : g_kb) + ((size_t)bh * NTOK + nx * 128) * 64;
#pragma unroll
        for (int i = 0; i < 4; i++) {
            int idx = tid + i * 256;
            int r = idx >> 3, c8 = idx & 7;
            *reinterpret_cast<uint4*>(dst + (size_t)r * 64 + c8 * 8) =
                *reinterpret_cast<uint4*>(&stage[r * 72 + c8 * 8]);
        }
    } else {
        __half* stage = &XTs[0][0];   // reused as [64][136]
        int chrow = (wid & 3) * 16 + r0;
#pragma unroll
        for (int nt = 0; nt < 8; nt++) {
            int col = (wid >> 2) * 64 + nt * 8 + cp;
            *reinterpret_cast<uint32_t*>(&stage[chrow * 136 + col])       = packh2(acc[nt][0], acc[nt][1]);
            *reinterpret_cast<uint32_t*>(&stage[(chrow + 8) * 136 + col]) = packh2(acc[nt][2], acc[nt][3]);
        }
        __syncthreads();
        __half* dst = g_vb + (size_t)bh * HD * NTOK + nx * 128;
#pragma unroll
        for (int i = 0; i < 4; i++) {
            int idx = tid + i * 256;
            int r = idx >> 4, c16 = idx & 15;
            *reinterpret_cast<uint4*>(dst + (size_t)r * NTOK + c16 * 8) =
                *reinterpret_cast<uint4*>(&stage[r * 136 + c16 * 8]);
        }
    }
}

// ---------------- HMMA flash attention (unchanged) ----------------
#define AQ_SZ   (128 * 72)
#define AK_SZ   (128 * 72)
#define AV_SZ   (64 * 136)
#define STG_SZ  (AK_SZ + AV_SZ)
#define ATTN_SMEM ((AQ_SZ + 2 * STG_SZ) * 2)

__global__ __launch_bounds__(128, 2) void attn_mma_kernel() {
    extern __shared__ __half sm[];
    __half* Qsm = sm;

    int tid = threadIdx.x, wid = tid >> 5, lane = tid & 31;
    int qb = blockIdx.x, bh = blockIdx.y;

    uint32_t sbase = smem_u32(sm);
    uint32_t Qb = sbase;
    uint32_t Kb[2] = {sbase + AQ_SZ * 2, sbase + (AQ_SZ + STG_SZ) * 2};
    uint32_t Vb[2] = {Kb[0] + AK_SZ * 2, Kb[1] + AK_SZ * 2};

    const __half* Kg_base = g_kb + (size_t)bh * NTOK * 64;
    const __half* Vg_base = g_vb + (size_t)bh * 64 * NTOK;

    auto load_kv = [&](int kb, int st) {
#pragma unroll
        for (int i = 0; i < 8; i++) {
            int idx = tid + i * 128;
            int r = idx >> 3, c8 = idx & 7;
            cp16(Kb[st] + (r * 72 + c8 * 8) * 2,
                 Kg_base + ((size_t)(kb * 128 + r)) * 64 + c8 * 8);
        }
#pragma unroll
        for (int i = 0; i < 8; i++) {
            int idx = tid + i * 128;
            int r = idx >> 4, c16 = idx & 15;
            cp16(Vb[st] + (r * 136 + c16 * 8) * 2,
                 Vg_base + (size_t)r * NTOK + kb * 128 + c16 * 8);
        }
    };

    {
        const uint4* Qg = reinterpret_cast<const uint4*>(g_qb + ((size_t)bh * NTOK + qb * 128) * 64);
#pragma unroll
        for (int i = 0; i < 8; i++) {
            int idx = tid + i * 128;
            int r = idx >> 3, c8 = idx & 7;
            *reinterpret_cast<uint4*>(Qsm + r * 72 + c8 * 8) = Qg[idx];
        }
    }
    load_kv(0, 0);
    CP_COMMIT();
    __syncthreads();

    uint32_t qf[2][4][4];
#pragma unroll
    for (int t = 0; t < 2; t++)
#pragma unroll
        for (int ks = 0; ks < 4; ks++) {
            uint32_t addr = Qb + ((wid * 32 + t * 16 + (lane & 15)) * 72 + ks * 16 + (lane >> 4) * 8) * 2;
            ldsm_x4(qf[t][ks][0], qf[t][ks][1], qf[t][ks][2], qf[t][ks][3], addr);
        }

    float oacc[2][8][4] = {};
    float l0[2] = {0.f, 0.f}, l1[2] = {0.f, 0.f};

    int btok = ((lane >> 4) << 3) + (lane & 7);
    int bk8  = lane & 8;

    for (int kb = 0; kb < 32; kb++) {
        int st = kb & 1;
        CP_WAIT(0);
        __syncthreads();
        if (kb + 1 < 32) { load_kv(kb + 1, st ^ 1); CP_COMMIT(); }

        uint32_t op[2][8][2] = {};

#pragma unroll
        for (int kt = 0; kt < 8; kt++) {
            uint32_t kf[4][4];
            {
                uint32_t ka = Kb[st] + ((kt * 16 + btok) * 72 + bk8) * 2;
#pragma unroll
                for (int ks = 0; ks < 4; ks++)
                    ldsm_x4(kf[ks][0], kf[ks][1], kf[ks][2], kf[ks][3], ka + ks * 32);
            }
            uint32_t vf[4][4];
            {
                uint32_t va = Vb[st] + (btok * 136 + kt * 16 + bk8) * 2;
#pragma unroll
                for (int j = 0; j < 4; j++)
                    ldsm_x4(vf[j][0], vf[j][1], vf[j][2], vf[j][3], va + j * 16 * 136 * 2);
            }

            uint32_t s[2][2][2] = {};
#pragma unroll
            for (int ks = 0; ks < 4; ks++) {
#pragma unroll
                for (int t = 0; t < 2; t++) {
                    mma_h16(s[t][0], qf[t][ks][0], qf[t][ks][1], qf[t][ks][2], qf[t][ks][3], kf[ks][0], kf[ks][1]);
                    mma_h16(s[t][1], qf[t][ks][0], qf[t][ks][1], qf[t][ks][2], qf[t][ks][3], kf[ks][2], kf[ks][3]);
                }
            }

#pragma unroll
            for (int t = 0; t < 2; t++) {
                uint32_t a0 = ex2h2(s[t][0][0]);
                uint32_t a1 = ex2h2(s[t][0][1]);
                uint32_t a2 = ex2h2(s[t][1][0]);
                uint32_t a3 = ex2h2(s[t][1][1]);
                float2 f0 = h22f2(hadd2u(a0, a2));
                float2 f1 = h22f2(hadd2u(a1, a3));
                l0[t] += f0.x + f0.y;
                l1[t] += f1.x + f1.y;
#pragma unroll
                for (int j = 0; j < 4; j++) {
                    mma_h16(op[t][2 * j],     a0, a1, a2, a3, vf[j][0], vf[j][1]);
                    mma_h16(op[t][2 * j + 1], a0, a1, a2, a3, vf[j][2], vf[j][3]);
                }
            }
        }

#pragma unroll
        for (int t = 0; t < 2; t++)
#pragma unroll
            for (int nt = 0; nt < 8; nt++) {
                float2 f0 = h22f2(op[t][nt][0]);
                float2 f1 = h22f2(op[t][nt][1]);
                oacc[t][nt][0] += f0.x; oacc[t][nt][1] += f0.y;
                oacc[t][nt][2] += f1.x; oacc[t][nt][3] += f1.y;
            }
    }

#pragma unroll
    for (int t = 0; t < 2; t++) {
        l0[t] += __shfl_xor_sync(0xffffffffu, l0[t], 1);
        l0[t] += __shfl_xor_sync(0xffffffffu, l0[t], 2);
        l1[t] += __shfl_xor_sync(0xffffffffu, l1[t], 1);
        l1[t] += __shfl_xor_sync(0xffffffffu, l1[t], 2);
    }

    __syncthreads();
    int r0 = lane >> 2, cpair = (lane & 3) << 1;
#pragma unroll
    for (int t = 0; t < 2; t++) {
        float inv0 = 1.f / l0[t], inv1 = 1.f / l1[t];
        int row = wid * 32 + t * 16 + r0;
#pragma unroll
        for (int nt = 0; nt < 8; nt++) {
            int col = nt * 8 + cpair;
            *reinterpret_cast<uint32_t*>(&Qsm[row * 72 + col])       = packh2(oacc[t][nt][0] * inv0, oacc[t][nt][1] * inv0);
            *reinterpret_cast<uint32_t*>(&Qsm[(row + 8) * 72 + col]) = packh2(oacc[t][nt][2] * inv1, oacc[t][nt][3] * inv1);
        }
    }
    __syncthreads();
    {
        int b = bh >> 2, h = bh & 3;
        __half* dst = g_ob + ((size_t)b * NTOK + qb * 128) * CC + h * 64;
#pragma unroll
        for (int i = 0; i < 8; i++) {
            int idx = tid + i * 128;
            int r = idx >> 3, c8 = idx & 7;
            *reinterpret_cast<uint4*>(dst + (size_t)r * CC + c8 * 8) =
                *reinterpret_cast<uint4*>(&Qsm[r * 72 + c8 * 8]);
        }
    }
}

// ---------------- output projection (HMMA, X double-buffered) + bias + residual ----------------
__global__ __launch_bounds__(256) void out_kernel(const float* __restrict__ wout,
                                                  const float* __restrict__ wout_b,
                                                  const float* __restrict__ inp,
                                                  float* __restrict__ out) {
    __shared__ __half XTs[2][128 * 72];
    __shared__ __half Ws[64 * 72];

    int tid = threadIdx.x, wid = tid >> 5, lane = tid & 31;
    int r0 = lane >> 2, cp = (lane & 3) << 1;
    int nx = blockIdx.x, my = blockIdx.y, b = blockIdx.z;

    const float* W = wout + (size_t)my * 64 * CC;
    const __half* X = g_ob + (size_t)b * NTOK * CC;

    uint32_t xbase[2] = {smem_u32(&XTs[0][0]), smem_u32(&XTs[1][0])};

    auto load_x = [&](int k0, int st) {
#pragma unroll
        for (int i = 0; i < 4; i++) {
            int idx = tid + i * 256;
            int r = idx >> 3, c8 = idx & 7;
            cp16(xbase[st] + (r * 72 + c8 * 8) * 2,
                 X + ((size_t)(nx * 128 + r)) * CC + k0 + c8 * 8);
        }
    };

    load_x(0, 0);
    CP_COMMIT();

    float acc[8][4] = {};

    for (int kc = 0; kc < 4; kc++) {
        int k0 = kc * 64, st = kc & 1;
#pragma unroll
        for (int i = 0; i < 4; i++) {
            int idx = tid + i * 256;
            int r = idx >> 4, c4 = (idx & 15) << 2;
            float4 w4 = *reinterpret_cast<const float4*>(W + (size_t)r * CC + k0 + c4);
            *reinterpret_cast<uint32_t*>(&Ws[r * 72 + c4])     = packh2(w4.x, w4.y);
            *reinterpret_cast<uint32_t*>(&Ws[r * 72 + c4 + 2]) = packh2(w4.z, w4.w);
        }
        CP_WAIT(0);
        __syncthreads();
        if (kc + 1 < 4) { load_x(k0 + 64, st ^ 1); CP_COMMIT(); }

        const __half* Xc = &XTs[st][0];
#pragma unroll
        for (int ks = 0; ks < 4; ks++) {
            const __half* Ar = Ws + ((wid & 3) * 16 + r0) * 72 + ks * 16 + cp;
            uint32_t a0 = *reinterpret_cast<const uint32_t*>(Ar);
            uint32_t a1 = *reinterpret_cast<const uint32_t*>(Ar + 8 * 72);
            uint32_t a2 = *reinterpret_cast<const uint32_t*>(Ar + 8);
            uint32_t a3 = *reinterpret_cast<const uint32_t*>(Ar + 8 * 72 + 8);
#pragma unroll
            for (int nt = 0; nt < 8; nt++) {
                const __half* Br = Xc + ((wid >> 2) * 64 + nt * 8 + r0) * 72 + ks * 16 + cp;
                uint32_t b0 = *reinterpret_cast<const uint32_t*>(Br);
                uint32_t b1 = *reinterpret_cast<const uint32_t*>(Br + 8);
                mma_f32(acc[nt], a0, a1, a2, a3, b0, b1);
            }
        }
        __syncthreads();
    }

    {
        int ch0 = my * 64 + (wid & 3) * 16 + r0;
        float bias0 = wout_b[ch0], bias1 = wout_b[ch0 + 8];
#pragma unroll
        for (int nt = 0; nt < 8; nt++) {
            int col = nx * 128 + (wid >> 2) * 64 + nt * 8 + cp;
            size_t off0 = ((size_t)b * CC + ch0) * NTOK + col;
            size_t off1 = off0 + (size_t)8 * NTOK;
            float2 rin0 = *reinterpret_cast<const float2*>(inp + off0);
            float2 rin1 = *reinterpret_cast<const float2*>(inp + off1);
            float2 v0 = {acc[nt][0] + bias0 + rin0.x, acc[nt][1] + bias0 + rin0.y};
            float2 v1 = {acc[nt][2] + bias1 + rin1.x, acc[nt][3] + bias1 + rin1.y};
            *reinterpret_cast<float2*>(out + off0) = v0;
            *reinterpret_cast<float2*>(out + off1) = v1;
        }
    }
}

// ---------------- launch ----------------
extern "C" void kernel_launch(void* const* d_in, const int* in_sizes, int n_in,
                              void* d_out, int out_size) {
    const float* input  = (const float*)d_in[0];
    const float* cctx   = (const float*)d_in[1];
    const float* gn_w   = (const float*)d_in[2];
    const float* gn_b   = (const float*)d_in[3];
    const float* wq     = (const float*)d_in[4];
    const float* wkv    = (const float*)d_in[5];
    const float* wout_w = (const float*)d_in[6];
    const float* wout_b = (const float*)d_in[7];
    float* out = (float*)d_out;

    static int smem_set = 0;
    if (!smem_set) {
        cudaFuncSetAttribute(attn_mma_kernel, cudaFuncAttributeMaxDynamicSharedMemorySize, ATTN_SMEM);
        smem_set = 1;
    }

    gn_xt_kernel<<<dim3(64, 2), 256>>>(input, cctx, gn_w, gn_b);
    qkv_kernel<<<dim3(32, 12, BB), 256>>>(wq, wkv);
    attn_mma_kernel<<<dim3(32, BB * NHEAD), 128, ATTN_SMEM>>>();
    out_kernel<<<dim3(32, 4, BB), 256>>>(wout_w, wout_b, input, out);
}

// round 16
// speedup vs baseline: 1.0566x; 1.0362x over previous
#include <cuda_runtime.h>
#include <cuda_fp16.h>
#include <cstdint>

#define BB 2
#define CC 256
#define NHEAD 4
#define HD 64
#define NTOK 4096

// ---------------- device scratch (fp16) ----------------
__device__ __half g_xq[BB*NTOK*CC];         // GN(input)^T  [b][tok][ch]
__device__ __half g_xk[BB*NTOK*CC];         // GN(c)^T      [b][tok][ch]
__device__ __half g_qb[BB*NHEAD*NTOK*HD];   // [bh][tok][d]  (pre-scaled by CEXP)
__device__ __half g_kb[BB*NHEAD*NTOK*HD];   // [bh][tok][d]
__device__ __half g_vb[BB*NHEAD*HD*NTOK];   // [bh][d][tok]
__device__ __half g_ob[BB*NTOK*CC];         // attn out     [b][tok][ch]

// ---------------- helpers ----------------
__device__ __forceinline__ void mma_f32(float* c, uint32_t a0, uint32_t a1, uint32_t a2,
                                        uint32_t a3, uint32_t b0, uint32_t b1) {
    asm volatile(
        "mma.sync.aligned.m16n8k16.row.col.f32.f16.f16.f32 "
        "{%0,%1,%2,%3}, {%4,%5,%6,%7}, {%8,%9}, {%0,%1,%2,%3};"
        : "+f"(c[0]), "+f"(c[1]), "+f"(c[2]), "+f"(c[3])
        : "r"(a0), "r"(a1), "r"(a2), "r"(a3), "r"(b0), "r"(b1));
}
__device__ __forceinline__ void mma_h16(uint32_t* c, uint32_t a0, uint32_t a1, uint32_t a2,
                                        uint32_t a3, uint32_t b0, uint32_t b1) {
    asm volatile(
        "mma.sync.aligned.m16n8k16.row.col.f16.f16.f16.f16 "
        "{%0,%1}, {%2,%3,%4,%5}, {%6,%7}, {%0,%1};"
        : "+r"(c[0]), "+r"(c[1])
        : "r"(a0), "r"(a1), "r"(a2), "r"(a3), "r"(b0), "r"(b1));
}
__device__ __forceinline__ uint32_t ex2h2(uint32_t x) {
    uint32_t r;
    asm("ex2.approx.f16x2 %0, %1;" : "=r"(r) : "r"(x));
    return r;
}
__device__ __forceinline__ uint32_t hadd2u(uint32_t a, uint32_t b) {
    uint32_t r;
    asm("add.f16x2 %0, %1, %2;" : "=r"(r) : "r"(a), "r"(b));
    return r;
}
__device__ __forceinline__ float2 h22f2(uint32_t u) {
    __half2 h = *reinterpret_cast<__half2*>(&u);
    return __half22float2(h);
}
__device__ __forceinline__ uint32_t packh2(float lo, float hi) {
    __half2 h = __floats2half2_rn(lo, hi);
    return *reinterpret_cast<uint32_t*>(&h);
}
__device__ __forceinline__ uint32_t smem_u32(const void* p) {
    uint32_t a;
    asm("{ .reg .u64 t; cvta.to.shared.u64 t, %1; cvt.u32.u64 %0, t; }" : "=r"(a) : "l"(p));
    return a;
}
__device__ __forceinline__ void ldsm_x4(uint32_t& r0, uint32_t& r1, uint32_t& r2, uint32_t& r3,
                                        uint32_t addr) {
    asm volatile("ldmatrix.sync.aligned.m8n8.x4.shared.b16 {%0,%1,%2,%3}, [%4];"
                 : "=r"(r0), "=r"(r1), "=r"(r2), "=r"(r3) : "r"(addr));
}
__device__ __forceinline__ void cp16(uint32_t saddr, const void* g) {
    asm volatile("cp.async.cg.shared.global [%0], [%1], 16;" :: "r"(saddr), "l"(g));
}
#define CP_COMMIT() asm volatile("cp.async.commit_group;" ::: "memory")
#define CP_WAIT(n)  asm volatile("cp.async.wait_group %0;" :: "n"(n) : "memory")

// ---------------- GroupNorm -> fp16 X^T [b][tok][256] (fused both sources, scalar pass 2) ----------------
__global__ __launch_bounds__(256) void gn_xt_kernel(const float* __restrict__ src0,
                                                    const float* __restrict__ src1,
                                                    const float* __restrict__ gw,
                                                    const float* __restrict__ gb) {
    int which = blockIdx.y;
    const float* src = which ? src1 : src0;
    int b = blockIdx.x >> 5, g = blockIdx.x & 31;
    size_t base = ((size_t)b * CC + g * 8) * NTOK;
    const float4* s4 = reinterpret_cast<const float4*>(src + base);
    int tid = threadIdx.x;

    float sum = 0.f, ssq = 0.f;
#pragma unroll
    for (int i = 0; i < 32; i++) {
        float4 v = s4[tid + i * 256];
        sum += v.x + v.y + v.z + v.w;
        ssq += v.x * v.x + v.y * v.y + v.z * v.z + v.w * v.w;
    }
#pragma unroll
    for (int off = 16; off; off >>= 1) {
        sum += __shfl_xor_sync(0xffffffffu, sum, off);
        ssq += __shfl_xor_sync(0xffffffffu, ssq, off);
    }
    __shared__ float r1[8], r2[8];
    if ((tid & 31) == 0) { r1[tid >> 5] = sum; r2[tid >> 5] = ssq; }
    __syncthreads();
    sum = 0.f; ssq = 0.f;
#pragma unroll
    for (int i = 0; i < 8; i++) { sum += r1[i]; ssq += r2[i]; }
    float mean = sum * (1.f / 32768.f);
    float var  = ssq * (1.f / 32768.f) - mean * mean;
    float rstd = rsqrtf(var + 1e-5f);

    float a[8], c0[8];
#pragma unroll
    for (int ch = 0; ch < 8; ch++) {
        a[ch]  = gw[g * 8 + ch] * rstd;
        c0[ch] = gb[g * 8 + ch] - mean * a[ch];
    }
    __half* xt = (which ? g_xk : g_xq) + (size_t)b * NTOK * CC + g * 8;
#pragma unroll
    for (int i = 0; i < 16; i++) {
        int tok = tid + i * 256;
        float v[8];
#pragma unroll
        for (int ch = 0; ch < 8; ch++)
            v[ch] = src[base + (size_t)ch * NTOK + tok] * a[ch] + c0[ch];
        uint4 u = {packh2(v[0], v[1]), packh2(v[2], v[3]),
                   packh2(v[4], v[5]), packh2(v[6], v[7])};
        *reinterpret_cast<uint4*>(xt + (size_t)tok * CC) = u;
    }
}

// ---------------- QKV projection via HMMA (X tiles double-buffered via cp.async) ----------------
__global__ __launch_bounds__(256) void qkv_kernel(const float* __restrict__ wq,
                                                  const float* __restrict__ wkv) {
    __shared__ __half XTs[2][128 * 72];
    __shared__ __half Ws[64 * 72];

    int tid = threadIdx.x, wid = tid >> 5, lane = tid & 31;
    int r0 = lane >> 2, cp = (lane & 3) << 1;
    int nx = blockIdx.x, role = blockIdx.y, b = blockIdx.z;

    const float* W;
    const __half* X;
    int h;
    bool is_v = (role >= 8);
    if (role < 4)      { h = role;     W = wq  + (size_t)h * 64 * CC;          X = g_xq + (size_t)b * NTOK * CC; }
    else if (role < 8) { h = role - 4; W = wkv + (size_t)(h * 128) * CC;       X = g_xk + (size_t)b * NTOK * CC; }
    else               { h = role - 8; W = wkv + (size_t)(h * 128 + 64) * CC;  X = g_xk + (size_t)b * NTOK * CC; }
    int bh = b * NHEAD + h;

    uint32_t xbase[2] = {smem_u32(&XTs[0][0]), smem_u32(&XTs[1][0])};

    auto load_x = [&](int k0, int st) {
#pragma unroll
        for (int i = 0; i < 4; i++) {
            int idx = tid + i * 256;
            int r = idx >> 3, c8 = idx & 7;
            cp16(xbase[st] + (r * 72 + c8 * 8) * 2,
                 X + ((size_t)(nx * 128 + r)) * CC + k0 + c8 * 8);
        }
    };

    load_x(0, 0);
    CP_COMMIT();

    float acc[8][4] = {};

    for (int kc = 0; kc < 4; kc++) {
        int k0 = kc * 64, st = kc & 1;
#pragma unroll
        for (int i = 0; i < 4; i++) {
            int idx = tid + i * 256;
            int r = idx >> 4, c4 = (idx & 15) << 2;
            float4 w4 = *reinterpret_cast<const float4*>(W + (size_t)r * CC + k0 + c4);
            *reinterpret_cast<uint32_t*>(&Ws[r * 72 + c4])     = packh2(w4.x, w4.y);
            *reinterpret_cast<uint32_t*>(&Ws[r * 72 + c4 + 2]) = packh2(w4.z, w4.w);
        }
        CP_WAIT(0);
        __syncthreads();
        if (kc + 1 < 4) { load_x(k0 + 64, st ^ 1); CP_COMMIT(); }

        const __half* Xc = &XTs[st][0];
        if (!is_v) {
#pragma unroll
            for (int ks = 0; ks < 4; ks++) {
                const __half* Ar = Xc + (wid * 16 + r0) * 72 + ks * 16 + cp;
                uint32_t a0 = *reinterpret_cast<const uint32_t*>(Ar);
                uint32_t a1 = *reinterpret_cast<const uint32_t*>(Ar + 8 * 72);
                uint32_t a2 = *reinterpret_cast<const uint32_t*>(Ar + 8);
                uint32_t a3 = *reinterpret_cast<const uint32_t*>(Ar + 8 * 72 + 8);
#pragma unroll
                for (int nt = 0; nt < 8; nt++) {
                    const __half* Br = Ws + (nt * 8 + r0) * 72 + ks * 16 + cp;
                    uint32_t b0 = *reinterpret_cast<const uint32_t*>(Br);
                    uint32_t b1 = *reinterpret_cast<const uint32_t*>(Br + 8);
                    mma_f32(acc[nt], a0, a1, a2, a3, b0, b1);
                }
            }
        } else {
#pragma unroll
            for (int ks = 0; ks < 4; ks++) {
                const __half* Ar = Ws + ((wid & 3) * 16 + r0) * 72 + ks * 16 + cp;
                uint32_t a0 = *reinterpret_cast<const uint32_t*>(Ar);
                uint32_t a1 = *reinterpret_cast<const uint32_t*>(Ar + 8 * 72);
                uint32_t a2 = *reinterpret_cast<const uint32_t*>(Ar + 8);
                uint32_t a3 = *reinterpret_cast<const uint32_t*>(Ar + 8 * 72 + 8);
#pragma unroll
                for (int nt = 0; nt < 8; nt++) {
                    const __half* Br = Xc + ((wid >> 2) * 64 + nt * 8 + r0) * 72 + ks * 16 + cp;
                    uint32_t b0 = *reinterpret_cast<const uint32_t*>(Br);
                    uint32_t b1 = *reinterpret_cast<const uint32_t*>(Br + 8);
                    mma_f32(acc[nt], a0, a1, a2, a3, b0, b1);
                }
            }
        }
        __syncthreads();
    }

    if (!is_v) {
        float qs = (role < 4) ? 0.09016844f : 1.0f;   // (1/16)*log2(e) folded into q
        __half* stage = &XTs[0][0];
        int row = wid * 16 + r0;
#pragma unroll
        for (int nt = 0; nt < 8; nt++) {
            int col = nt * 8 + cp;
            *reinterpret_cast<uint32_t*>(&stage[row * 72 + col])       = packh2(acc[nt][0] * qs, acc[nt][1] * qs);
            *reinterpret_cast<uint32_t*>(&stage[(row + 8) * 72 + col]) = packh2(acc[nt][2] * qs, acc[nt][3] * qs);
        }
        __syncthreads();
        __half* dst = (role < 4 ? g_qb : g_kb) + ((size_t)bh * NTOK + nx * 128) * 64;
#pragma unroll
        for (int i = 0; i < 4; i++) {
            int idx = tid + i * 256;
            int r = idx >> 3, c8 = idx & 7;
            *reinterpret_cast<uint4*>(dst + (size_t)r * 64 + c8 * 8) =
                *reinterpret_cast<uint4*>(&stage[r * 72 + c8 * 8]);
        }
    } else {
        __half* stage = &XTs[0][0];   // reused as [64][136]
        int chrow = (wid & 3) * 16 + r0;
#pragma unroll
        for (int nt = 0; nt < 8; nt++) {
            int col = (wid >> 2) * 64 + nt * 8 + cp;
            *reinterpret_cast<uint32_t*>(&stage[chrow * 136 + col])       = packh2(acc[nt][0], acc[nt][1]);
            *reinterpret_cast<uint32_t*>(&stage[(chrow + 8) * 136 + col]) = packh2(acc[nt][2], acc[nt][3]);
        }
        __syncthreads();
        __half* dst = g_vb + (size_t)bh * HD * NTOK + nx * 128;
#pragma unroll
        for (int i = 0; i < 4; i++) {
            int idx = tid + i * 256;
            int r = idx >> 4, c16 = idx & 15;
            *reinterpret_cast<uint4*>(dst + (size_t)r * NTOK + c16 * 8) =
                *reinterpret_cast<uint4*>(&stage[r * 136 + c16 * 8]);
        }
    }
}

// ---------------- HMMA flash attention ----------------
#define AQ_SZ   (128 * 72)
#define AK_SZ   (128 * 72)
#define AV_SZ   (64 * 136)
#define STG_SZ  (AK_SZ + AV_SZ)
#define ATTN_SMEM ((AQ_SZ + 2 * STG_SZ) * 2)

__global__ __launch_bounds__(128, 2) void attn_mma_kernel() {
    extern __shared__ __half sm[];
    __half* Qsm = sm;

    int tid = threadIdx.x, wid = tid >> 5, lane = tid & 31;
    int qb = blockIdx.x, bh = blockIdx.y;

    uint32_t sbase = smem_u32(sm);
    uint32_t Qb = sbase;
    uint32_t Kb[2] = {sbase + AQ_SZ * 2, sbase + (AQ_SZ + STG_SZ) * 2};
    uint32_t Vb[2] = {Kb[0] + AK_SZ * 2, Kb[1] + AK_SZ * 2};

    const __half* Kg_base = g_kb + (size_t)bh * NTOK * 64;
    const __half* Vg_base = g_vb + (size_t)bh * 64 * NTOK;

    auto load_kv = [&](int kb, int st) {
#pragma unroll
        for (int i = 0; i < 8; i++) {
            int idx = tid + i * 128;
            int r = idx >> 3, c8 = idx & 7;
            cp16(Kb[st] + (r * 72 + c8 * 8) * 2,
                 Kg_base + ((size_t)(kb * 128 + r)) * 64 + c8 * 8);
        }
#pragma unroll
        for (int i = 0; i < 8; i++) {
            int idx = tid + i * 128;
            int r = idx >> 4, c16 = idx & 15;
            cp16(Vb[st] + (r * 136 + c16 * 8) * 2,
                 Vg_base + (size_t)r * NTOK + kb * 128 + c16 * 8);
        }
    };

    {
        const uint4* Qg = reinterpret_cast<const uint4*>(g_qb + ((size_t)bh * NTOK + qb * 128) * 64);
#pragma unroll
        for (int i = 0; i < 8; i++) {
            int idx = tid + i * 128;
            int r = idx >> 3, c8 = idx & 7;
            *reinterpret_cast<uint4*>(Qsm + r * 72 + c8 * 8) = Qg[idx];
        }
    }
    load_kv(0, 0);
    CP_COMMIT();
    __syncthreads();

    uint32_t qf[2][4][4];
#pragma unroll
    for (int t = 0; t < 2; t++)
#pragma unroll
        for (int ks = 0; ks < 4; ks++) {
            uint32_t addr = Qb + ((wid * 32 + t * 16 + (lane & 15)) * 72 + ks * 16 + (lane >> 4) * 8) * 2;
            ldsm_x4(qf[t][ks][0], qf[t][ks][1], qf[t][ks][2], qf[t][ks][3], addr);
        }

    float oacc[2][8][4] = {};
    float l0[2] = {0.f, 0.f}, l1[2] = {0.f, 0.f};

    int btok = ((lane >> 4) << 3) + (lane & 7);
    int bk8  = lane & 8;

    for (int kb = 0; kb < 32; kb++) {
        int st = kb & 1;
        CP_WAIT(0);
        __syncthreads();
        if (kb + 1 < 32) { load_kv(kb + 1, st ^ 1); CP_COMMIT(); }

        uint32_t op[2][8][2] = {};

#pragma unroll
        for (int kt = 0; kt < 8; kt++) {
            uint32_t kf[4][4];
            {
                uint32_t ka = Kb[st] + ((kt * 16 + btok) * 72 + bk8) * 2;
#pragma unroll
                for (int ks = 0; ks < 4; ks++)
                    ldsm_x4(kf[ks][0], kf[ks][1], kf[ks][2], kf[ks][3], ka + ks * 32);
            }
            uint32_t vf[4][4];
            {
                uint32_t va = Vb[st] + (btok * 136 + kt * 16 + bk8) * 2;
#pragma unroll
                for (int j = 0; j < 4; j++)
                    ldsm_x4(vf[j][0], vf[j][1], vf[j][2], vf[j][3], va + j * 16 * 136 * 2);
            }

            uint32_t s[2][2][2] = {};
#pragma unroll
            for (int ks = 0; ks < 4; ks++) {
#pragma unroll
                for (int t = 0; t < 2; t++) {
                    mma_h16(s[t][0], qf[t][ks][0], qf[t][ks][1], qf[t][ks][2], qf[t][ks][3], kf[ks][0], kf[ks][1]);
                    mma_h16(s[t][1], qf[t][ks][0], qf[t][ks][1], qf[t][ks][2], qf[t][ks][3], kf[ks][2], kf[ks][3]);
                }
            }

#pragma unroll
            for (int t = 0; t < 2; t++) {
                uint32_t a0 = ex2h2(s[t][0][0]);
                uint32_t a1 = ex2h2(s[t][0][1]);
                uint32_t a2 = ex2h2(s[t][1][0]);
                uint32_t a3 = ex2h2(s[t][1][1]);
                float2 f0 = h22f2(hadd2u(a0, a2));
                float2 f1 = h22f2(hadd2u(a1, a3));
                l0[t] += f0.x + f0.y;
                l1[t] += f1.x + f1.y;
#pragma unroll
                for (int j = 0; j < 4; j++) {
                    mma_h16(op[t][2 * j],     a0, a1, a2, a3, vf[j][0], vf[j][1]);
                    mma_h16(op[t][2 * j + 1], a0, a1, a2, a3, vf[j][2], vf[j][3]);
                }
            }
        }

#pragma unroll
        for (int t = 0; t < 2; t++)
#pragma unroll
            for (int nt = 0; nt < 8; nt++) {
                float2 f0 = h22f2(op[t][nt][0]);
                float2 f1 = h22f2(op[t][nt][1]);
                oacc[t][nt][0] += f0.x; oacc[t][nt][1] += f0.y;
                oacc[t][nt][2] += f1.x; oacc[t][nt][3] += f1.y;
            }
    }

#pragma unroll
    for (int t = 0; t < 2; t++) {
        l0[t] += __shfl_xor_sync(0xffffffffu, l0[t], 1);
        l0[t] += __shfl_xor_sync(0xffffffffu, l0[t], 2);
        l1[t] += __shfl_xor_sync(0xffffffffu, l1[t], 1);
        l1[t] += __shfl_xor_sync(0xffffffffu, l1[t], 2);
    }

    __syncthreads();
    int r0 = lane >> 2, cpair = (lane & 3) << 1;
#pragma unroll
    for (int t = 0; t < 2; t++) {
        float inv0 = 1.f / l0[t], inv1 = 1.f / l1[t];
        int row = wid * 32 + t * 16 + r0;
#pragma unroll
        for (int nt = 0; nt < 8; nt++) {
            int col = nt * 8 + cpair;
            *reinterpret_cast<uint32_t*>(&Qsm[row * 72 + col])       = packh2(oacc[t][nt][0] * inv0, oacc[t][nt][1] * inv0);
            *reinterpret_cast<uint32_t*>(&Qsm[(row + 8) * 72 + col]) = packh2(oacc[t][nt][2] * inv1, oacc[t][nt][3] * inv1);
        }
    }
    __syncthreads();
    {
        int b = bh >> 2, h = bh & 3;
        __half* dst = g_ob + ((size_t)b * NTOK + qb * 128) * CC + h * 64;
#pragma unroll
        for (int i = 0; i < 8; i++) {
            int idx = tid + i * 128;
            int r = idx >> 3, c8 = idx & 7;
            *reinterpret_cast<uint4*>(dst + (size_t)r * CC + c8 * 8) =
                *reinterpret_cast<uint4*>(&Qsm[r * 72 + c8 * 8]);
        }
    }
}

// ---------------- output projection (HMMA, X double-buffered) + bias + residual ----------------
__global__ __launch_bounds__(256) void out_kernel(const float* __restrict__ wout,
                                                  const float* __restrict__ wout_b,
                                                  const float* __restrict__ inp,
                                                  float* __restrict__ out) {
    __shared__ __half XTs[2][128 * 72];
    __shared__ __half Ws[64 * 72];

    int tid = threadIdx.x, wid = tid >> 5, lane = tid & 31;
    int r0 = lane >> 2, cp = (lane & 3) << 1;
    int nx = blockIdx.x, my = blockIdx.y, b = blockIdx.z;

    const float* W = wout + (size_t)my * 64 * CC;
    const __half* X = g_ob + (size_t)b * NTOK * CC;

    uint32_t xbase[2] = {smem_u32(&XTs[0][0]), smem_u32(&XTs[1][0])};

    auto load_x = [&](int k0, int st) {
#pragma unroll
        for (int i = 0; i < 4; i++) {
            int idx = tid + i * 256;
            int r = idx >> 3, c8 = idx & 7;
            cp16(xbase[st] + (r * 72 + c8 * 8) * 2,
                 X + ((size_t)(nx * 128 + r)) * CC + k0 + c8 * 8);
        }
    };

    load_x(0, 0);
    CP_COMMIT();

    float acc[8][4] = {};

    for (int kc = 0; kc < 4; kc++) {
        int k0 = kc * 64, st = kc & 1;
#pragma unroll
        for (int i = 0; i < 4; i++) {
            int idx = tid + i * 256;
            int r = idx >> 4, c4 = (idx & 15) << 2;
            float4 w4 = *reinterpret_cast<const float4*>(W + (size_t)r * CC + k0 + c4);
            *reinterpret_cast<uint32_t*>(&Ws[r * 72 + c4])     = packh2(w4.x, w4.y);
            *reinterpret_cast<uint32_t*>(&Ws[r * 72 + c4 + 2]) = packh2(w4.z, w4.w);
        }
        CP_WAIT(0);
        __syncthreads();
        if (kc + 1 < 4) { load_x(k0 + 64, st ^ 1); CP_COMMIT(); }

        const __half* Xc = &XTs[st][0];
#pragma unroll
        for (int ks = 0; ks < 4; ks++) {
            const __half* Ar = Ws + ((wid & 3) * 16 + r0) * 72 + ks * 16 + cp;
            uint32_t a0 = *reinterpret_cast<const uint32_t*>(Ar);
            uint32_t a1 = *reinterpret_cast<const uint32_t*>(Ar + 8 * 72);
            uint32_t a2 = *reinterpret_cast<const uint32_t*>(Ar + 8);
            uint32_t a3 = *reinterpret_cast<const uint32_t*>(Ar + 8 * 72 + 8);
#pragma unroll
            for (int nt = 0; nt < 8; nt++) {
                const __half* Br = Xc + ((wid >> 2) * 64 + nt * 8 + r0) * 72 + ks * 16 + cp;
                uint32_t b0 = *reinterpret_cast<const uint32_t*>(Br);
                uint32_t b1 = *reinterpret_cast<const uint32_t*>(Br + 8);
                mma_f32(acc[nt], a0, a1, a2, a3, b0, b1);
            }
        }
        __syncthreads();
    }

    {
        int ch0 = my * 64 + (wid & 3) * 16 + r0;
        float bias0 = wout_b[ch0], bias1 = wout_b[ch0 + 8];
#pragma unroll
        for (int nt = 0; nt < 8; nt++) {
            int col = nx * 128 + (wid >> 2) * 64 + nt * 8 + cp;
            size_t off0 = ((size_t)b * CC + ch0) * NTOK + col;
            size_t off1 = off0 + (size_t)8 * NTOK;
            float2 rin0 = *reinterpret_cast<const float2*>(inp + off0);
            float2 rin1 = *reinterpret_cast<const float2*>(inp + off1);
            float2 v0 = {acc[nt][0] + bias0 + rin0.x, acc[nt][1] + bias0 + rin0.y};
            float2 v1 = {acc[nt][2] + bias1 + rin1.x, acc[nt][3] + bias1 + rin1.y};
            *reinterpret_cast<float2*>(out + off0) = v0;
            *reinterpret_cast<float2*>(out + off1) = v1;
        }
    }
}

// ---------------- launch ----------------
extern "C" void kernel_launch(void* const* d_in, const int* in_sizes, int n_in,
                              void* d_out, int out_size) {
    const float* input  = (const float*)d_in[0];
    const float* cctx   = (const float*)d_in[1];
    const float* gn_w   = (const float*)d_in[2];
    const float* gn_b   = (const float*)d_in[3];
    const float* wq     = (const float*)d_in[4];
    const float* wkv    = (const float*)d_in[5];
    const float* wout_w = (const float*)d_in[6];
    const float* wout_b = (const float*)d_in[7];
    float* out = (float*)d_out;

    static int smem_set = 0;
    if (!smem_set) {
        cudaFuncSetAttribute(attn_mma_kernel, cudaFuncAttributeMaxDynamicSharedMemorySize, ATTN_SMEM);
        smem_set = 1;
    }

    gn_xt_kernel<<<dim3(64, 2), 256>>>(input, cctx, gn_w, gn_b);
    qkv_kernel<<<dim3(32, 12, BB), 256>>>(wq, wkv);
    attn_mma_kernel<<<dim3(32, BB * NHEAD), 128, ATTN_SMEM>>>();
    out_kernel<<<dim3(32, 4, BB), 256>>>(wout_w, wout_b, input, out);
}